// round 4
// baseline (speedup 1.0000x reference)
#include <cuda_runtime.h>
#include <cstdint>
#include <math.h>

#define BB   4
#define CH   32
#define GCH  384
#define HH   224
#define WW   224
#define HW   50176
#define NPLANE 6422528        // 4*32*224*224
#define N4     1605632        // NPLANE/4
#define WT   4                // scan tile width (steps per SMEM tile)
#define SSTR 232              // padded SMEM row stride
#define TBUF (WT * SSTR)      // 928 floats per tile array

// Scratch (static device globals)
__device__ __align__(16) float g_y32[NPLANE];        // conv1 output
__device__ __align__(16) float g_dirA[4 * NPLANE];   // pass-1 directional outputs
__device__ __align__(16) float g_dirB[4 * NPLANE];   // pass-2 directional outputs
__device__ __align__(16) float g_s1[NPLANE];         // max of pass-1

__device__ __forceinline__ void cpa4(unsigned int saddr, const float* g)
{
    asm volatile("cp.async.ca.shared.global [%0], [%1], 4;\n"
                 :: "r"(saddr), "l"(g));
}

// ---------------------------------------------------------------------------
// conv1: y [4,2,224,224] -> g_y32 [4,32,224,224], 3x3 same
// ---------------------------------------------------------------------------
__global__ void __launch_bounds__(224) conv1_kernel(
    const float* __restrict__ y, const float* __restrict__ w3)
{
    int b = blockIdx.x / HH;
    int h = blockIdx.x % HH;
    int tid = threadIdx.x;

    __shared__ float si[2][3][WW + 2];
    __shared__ float sw[32 * 2 * 9];

    for (int i = tid; i < 576; i += 224) sw[i] = w3[i];

    #pragma unroll
    for (int ic = 0; ic < 2; ic++)
        #pragma unroll
        for (int r = 0; r < 3; r++) {
            int hh = h + r - 1;
            float v = (hh >= 0 && hh < HH)
                        ? y[((size_t)(b * 2 + ic) * HH + hh) * WW + tid] : 0.f;
            si[ic][r][tid + 1] = v;
            if (tid < 2) si[ic][r][tid * (WW + 1)] = 0.f;
        }
    __syncthreads();

    float v[18];
    #pragma unroll
    for (int ic = 0; ic < 2; ic++)
        #pragma unroll
        for (int r = 0; r < 3; r++)
            #pragma unroll
            for (int dx = 0; dx < 3; dx++)
                v[ic * 9 + r * 3 + dx] = si[ic][r][tid + dx];

    for (int oc = 0; oc < 32; oc++) {
        float acc = 0.f;
        #pragma unroll
        for (int k = 0; k < 18; k++) acc = fmaf(v[k], sw[oc * 18 + k], acc);
        g_y32[((size_t)(b * 32 + oc) * HH + h) * WW + tid] = acc;
    }
}

// ---------------------------------------------------------------------------
// Propagation with cp.async double-buffered tiles, 4 CTAs/SM (one wave).
// dir map: 0=lr(hor,fwd) 1=rl(vert,rev) 2=du(vert,fwd) 3=ud(hor,rev)
// ---------------------------------------------------------------------------
__global__ void __launch_bounds__(224, 4) prop_kernel(
    const float* __restrict__ gates, int pass)
{
    int pid = blockIdx.x;           // 0..511
    int d  = pid >> 7;
    int bc = pid & 127;
    int b  = bc >> 5;
    int c  = bc & 31;
    bool hor = (d == 0 || d == 3);
    bool rev = (d == 1 || d == 3);

    const float* xin = pass ? g_s1 : g_y32;
    const float* xp  = xin + (size_t)bc * HW;
    float*       op  = (pass ? g_dirB : g_dirA) + (size_t)(d * 128 + bc) * HW;
    const float* g1p = gates + ((size_t)b * GCH + d * 96 + c) * HW;
    const float* g2p = g1p + (size_t)32 * HW;
    const float* g3p = g1p + (size_t)64 * HW;
    const float* gp[4] = { xp, g1p, g2p, g3p };

    __shared__ float bufs[2][4][TBUF];
    __shared__ float to[TBUF];
    __shared__ float hb[2][WW + 2];

    int tid = threadIdx.x;
    for (int i = tid; i < 2 * (WW + 2); i += 224) ((float*)hb)[i] = 0.f;

    unsigned int sb0 = (unsigned int)__cvta_generic_to_shared(&bufs[0][0][0]);

    auto prefetch = [&](int tb, int buf) {
        unsigned int base = sb0 + (unsigned int)buf * (4u * TBUF * 4u);
        if (hor) {
            #pragma unroll
            for (int i = 0; i < WT; i++) {
                int idx = i * 224 + tid;
                int s = idx >> 2, j = idx & 3;
                int tg = rev ? (223 - tb * WT - j) : (tb * WT + j);
                int off = s * WW + tg;
                unsigned int m = (unsigned int)(j * SSTR + s) * 4u;
                #pragma unroll
                for (int a = 0; a < 4; a++)
                    cpa4(base + (unsigned int)a * (TBUF * 4u) + m, gp[a] + off);
            }
        } else {
            #pragma unroll
            for (int i = 0; i < WT; i++) {
                int tg = rev ? (223 - tb * WT - i) : (tb * WT + i);
                int off = tg * WW + tid;
                unsigned int m = (unsigned int)(i * SSTR + tid) * 4u;
                #pragma unroll
                for (int a = 0; a < 4; a++)
                    cpa4(base + (unsigned int)a * (TBUF * 4u) + m, gp[a] + off);
            }
        }
        asm volatile("cp.async.commit_group;");
    };

    prefetch(0, 0);
    float hreg = 0.f;

    for (int tb = 0; tb < HH / WT; tb++) {
        int cur = tb & 1;
        if (tb + 1 < HH / WT) {
            prefetch(tb + 1, cur ^ 1);
            asm volatile("cp.async.wait_group 1;");
        } else {
            asm volatile("cp.async.wait_group 0;");
        }
        __syncthreads();           // tile tb visible to all threads

        const float* bx = bufs[cur][0];
        const float* b1 = bufs[cur][1];
        const float* b2 = bufs[cur][2];
        const float* b3 = bufs[cur][3];

        // Stage + pre-normalize this tile's gates into registers
        float sb[WT], s1[WT], s2[WT], s3[WT];
        #pragma unroll
        for (int j = 0; j < WT; j++) {
            int m = j * SSTR + tid;
            float a1 = b1[m], a2 = b2[m], a3 = b3[m], xv = bx[m];
            float inv = __fdividef(1.0f,
                          fmaxf(fabsf(a1) + fabsf(a2) + fabsf(a3), 1.0f));
            s1[j] = a1 * inv;
            s2[j] = a2 * inv;
            s3[j] = a3 * inv;
            sb[j] = (1.0f - (a1 + a2 + a3) * inv) * xv;
        }

        int t0 = tb * WT;
        #pragma unroll
        for (int j = 0; j < WT; j++) {
            const float* hp = hb[(t0 + j) & 1];
            float*       hc = hb[((t0 + j) & 1) ^ 1];
            float hn = fmaf(s1[j], hp[tid],
                       fmaf(s2[j], hreg,
                       fmaf(s3[j], hp[tid + 2], sb[j])));
            hc[tid + 1] = hn;
            to[j * SSTR + tid] = hn;
            hreg = hn;
            __syncthreads();
        }

        // Flush output tile (coalesced)
        if (hor) {
            #pragma unroll
            for (int i = 0; i < WT; i++) {
                int idx = i * 224 + tid;
                int s = idx >> 2, j = idx & 3;
                int tg = rev ? (223 - t0 - j) : (t0 + j);
                op[s * WW + tg] = to[j * SSTR + s];
            }
        } else {
            #pragma unroll
            for (int i = 0; i < WT; i++) {
                int tg = rev ? (223 - t0 - i) : (t0 + i);
                op[tg * WW + tid] = to[i * SSTR + tid];
            }
        }
    }
}

// ---------------------------------------------------------------------------
// max over 4 pass-1 direction buffers -> g_s1
// ---------------------------------------------------------------------------
__global__ void max_kernel()
{
    int i = blockIdx.x * blockDim.x + threadIdx.x;
    if (i >= N4) return;
    const float4* d0 = (const float4*)g_dirA;
    float4 a = d0[i];
    float4 b = d0[i + N4];
    float4 c = d0[i + 2 * N4];
    float4 e = d0[i + 3 * N4];
    float4 r;
    r.x = fmaxf(fmaxf(a.x, b.x), fmaxf(c.x, e.x));
    r.y = fmaxf(fmaxf(a.y, b.y), fmaxf(c.y, e.y));
    r.z = fmaxf(fmaxf(a.z, b.z), fmaxf(c.z, e.z));
    r.w = fmaxf(fmaxf(a.w, b.w), fmaxf(c.w, e.w));
    ((float4*)g_s1)[i] = r;
}

// ---------------------------------------------------------------------------
// conv2 (32->2, 3x3 same) fused with max over 4 pass-2 dirs + log_softmax
// ---------------------------------------------------------------------------
__global__ void __launch_bounds__(224) conv2_ls_kernel(
    const float* __restrict__ w4, float* __restrict__ out)
{
    int b = blockIdx.x / HH;
    int h = blockIdx.x % HH;
    int tid = threadIdx.x;

    __shared__ float si[16][3][WW + 2];
    __shared__ float sw[2 * 32 * 9];

    for (int i = tid; i < 576; i += 224) sw[i] = w4[i];

    float acc0 = 0.f, acc1 = 0.f;

    for (int chunk = 0; chunk < 2; chunk++) {
        __syncthreads();
        for (int icl = 0; icl < 16; icl++) {
            int ic = chunk * 16 + icl;
            #pragma unroll
            for (int r = 0; r < 3; r++) {
                int hh = h + r - 1;
                float v = 0.f;
                if (hh >= 0 && hh < HH) {
                    size_t base = ((size_t)(b * 32 + ic) * HH + hh) * WW + tid;
                    float v0 = g_dirB[base];
                    float v1 = g_dirB[base + 1 * (size_t)NPLANE];
                    float v2 = g_dirB[base + 2 * (size_t)NPLANE];
                    float v3 = g_dirB[base + 3 * (size_t)NPLANE];
                    v = fmaxf(fmaxf(v0, v1), fmaxf(v2, v3));
                }
                si[icl][r][tid + 1] = v;
                if (tid < 2) si[icl][r][tid * (WW + 1)] = 0.f;
            }
        }
        __syncthreads();
        for (int icl = 0; icl < 16; icl++) {
            int ic = chunk * 16 + icl;
            #pragma unroll
            for (int r = 0; r < 3; r++)
                #pragma unroll
                for (int dx = 0; dx < 3; dx++) {
                    float v = si[icl][r][tid + dx];
                    int k = ic * 9 + r * 3 + dx;
                    acc0 = fmaf(v, sw[k], acc0);
                    acc1 = fmaf(v, sw[288 + k], acc1);
                }
        }
    }

    float m  = fmaxf(acc0, acc1);
    float e0 = __expf(acc0 - m), e1 = __expf(acc1 - m);
    float lse = m + __logf(e0 + e1);
    size_t o = ((size_t)b * 2 * HH + h) * WW + tid;
    out[o]      = acc0 - lse;
    out[o + HW] = acc1 - lse;
}

// ---------------------------------------------------------------------------
extern "C" void kernel_launch(void* const* d_in, const int* in_sizes, int n_in,
                              void* d_out, int out_size)
{
    const float* gates = (const float*)d_in[0];  // [4,384,224,224]
    const float* y     = (const float*)d_in[1];  // [4,2,224,224]
    const float* w3    = (const float*)d_in[2];  // [32,2,3,3]
    const float* w4    = (const float*)d_in[3];  // [2,32,3,3]
    float* out = (float*)d_out;                  // [4,2,224,224]

    (void)in_sizes; (void)n_in; (void)out_size;

    conv1_kernel<<<BB * HH, 224>>>(y, w3);
    prop_kernel<<<512, 224>>>(gates, 0);     // -> g_dirA
    max_kernel<<<(N4 + 255) / 256, 256>>>(); // g_dirA -> g_s1
    prop_kernel<<<512, 224>>>(gates, 1);     // x=g_s1 -> g_dirB
    conv2_ls_kernel<<<BB * HH, 224>>>(w4, out);
}